// round 6
// baseline (speedup 1.0000x reference)
#include <cuda_runtime.h>
#include <math.h>

// Shapes fixed by the problem instance.
#define B_SZ 2048
#define P_SZ 4
#define N_SZ 128
#define D_SZ 1024
#define S_SZ (N_SZ + 1)      // 129 samples: [last positive, negatives...]
#define EPS_F 1e-6f

#define THREADS 256
#define NWARP (THREADS / 32)

// Fixed-point accumulation of the (non-negative) per-batch losses at 2^-22
// resolution. Integer reduction is exact and commutative -> deterministic.
#define SCALE_F   4194304.0f              // 2^22
#define INV_SCALE (1.0f / 8589934592.0f)  // 1 / (2^22 * 2048)

// Scratch (no cudaMalloc allowed). Reset by the finalize kernel each run.
__device__ unsigned long long g_sum = 0ULL;

__global__ __launch_bounds__(THREADS)
void contrastive_sim_kernel(const float* __restrict__ anchor,
                            const float* __restrict__ positives,
                            const float* __restrict__ negatives) {
    const int b    = blockIdx.x;
    const int tid  = threadIdx.x;
    const int warp = tid >> 5;
    const int lane = tid & 31;

    __shared__ float4 sa[D_SZ / 4];   // anchor row, 4 KB
    __shared__ float  sims[S_SZ];
    __shared__ float  red[NWARP];
    __shared__ float  s_na;

    // ---- load anchor into smem, accumulate ||a||^2 ----
    const float4* ap = reinterpret_cast<const float4*>(anchor + (size_t)b * D_SZ);
    float asq = 0.f;
    #pragma unroll
    for (int i = tid; i < D_SZ / 4; i += THREADS) {
        float4 v = ap[i];
        sa[i] = v;
        asq += v.x * v.x + v.y * v.y + v.z * v.z + v.w * v.w;
    }
    #pragma unroll
    for (int o = 16; o; o >>= 1) asq += __shfl_down_sync(0xffffffffu, asq, o);
    if (lane == 0) red[warp] = asq;
    __syncthreads();
    if (warp == 0) {
        float v = (lane < NWARP) ? red[lane] : 0.f;
        #pragma unroll
        for (int o = 16; o; o >>= 1) v += __shfl_down_sync(0xffffffffu, v, o);
        if (lane == 0) s_na = fmaxf(sqrtf(v), EPS_F);
    }
    __syncthreads();
    const float na = s_na;

    // ---- each warp: cosine sim for its samples ----
    for (int s = warp; s < S_SZ; s += NWARP) {
        const float4* xp;
        if (s == 0)
            xp = reinterpret_cast<const float4*>(
                positives + ((size_t)b * P_SZ + (P_SZ - 1)) * D_SZ);
        else
            xp = reinterpret_cast<const float4*>(
                negatives + ((size_t)b * N_SZ + (s - 1)) * D_SZ);

        float dot = 0.f, nsq = 0.f;
        #pragma unroll
        for (int i = 0; i < D_SZ / 4 / 32; i++) {   // 8 coalesced float4 loads/lane
            int idx = i * 32 + lane;
            float4 x = xp[idx];
            float4 a = sa[idx];
            dot += a.x * x.x + a.y * x.y + a.z * x.z + a.w * x.w;
            nsq += x.x * x.x + x.y * x.y + x.z * x.z + x.w * x.w;
        }
        #pragma unroll
        for (int o = 16; o; o >>= 1) {
            dot += __shfl_down_sync(0xffffffffu, dot, o);
            nsq += __shfl_down_sync(0xffffffffu, nsq, o);
        }
        if (lane == 0) {
            float ns = fmaxf(sqrtf(nsq), EPS_F);
            sims[s] = dot / (na * ns);
        }
    }
    __syncthreads();

    // ---- warp 0: log-softmax over 129 values, no-return reduction ----
    if (warp == 0) {
        float m = -1e30f;
        for (int s = lane; s < S_SZ; s += 32) m = fmaxf(m, sims[s]);
        #pragma unroll
        for (int o = 16; o; o >>= 1) m = fmaxf(m, __shfl_xor_sync(0xffffffffu, m, o));
        float sum = 0.f;
        for (int s = lane; s < S_SZ; s += 32) sum += __expf(sims[s] - m);
        #pragma unroll
        for (int o = 16; o; o >>= 1) sum += __shfl_xor_sync(0xffffffffu, sum, o);

        if (lane == 0) {
            float loss = -(sims[0] - m - __logf(sum));   // >= 0
            unsigned long long q =
                (unsigned long long)(loss * SCALE_F + 0.5f);
            // Fire-and-forget REDG: no return value, no retirement stall,
            // ~1 cyc/op at the LTS even for a single shared address.
            asm volatile(
                "red.global.add.u64 [%0], %1;"
                :: "l"(&g_sum), "l"(q) : "memory");
        }
    }
}

__global__ void contrastive_finalize_kernel(float* __restrict__ out) {
    // PDL: wait for the sim grid's completion (and memory visibility).
    cudaGridDependencySynchronize();
    unsigned long long total = g_sum;
    *out = (float)total * INV_SCALE;
    g_sum = 0ULL;    // reset for next graph replay
}

extern "C" void kernel_launch(void* const* d_in, const int* in_sizes, int n_in,
                              void* d_out, int out_size) {
    const float* anchor    = (const float*)d_in[0];
    const float* positives = (const float*)d_in[1];
    const float* negatives = (const float*)d_in[2];
    float* out = (float*)d_out;

    contrastive_sim_kernel<<<B_SZ, THREADS>>>(anchor, positives, negatives);

    // Trivial finalize, overlapped via programmatic dependent launch.
    cudaLaunchConfig_t cfg = {};
    cfg.gridDim  = dim3(1, 1, 1);
    cfg.blockDim = dim3(1, 1, 1);
    cfg.dynamicSmemBytes = 0;
    cfg.stream = 0;
    cudaLaunchAttribute attrs[1];
    attrs[0].id = cudaLaunchAttributeProgrammaticStreamSerialization;
    attrs[0].val.programmaticStreamSerializationAllowed = 1;
    cfg.attrs = attrs;
    cfg.numAttrs = 1;
    cudaLaunchKernelEx(&cfg, contrastive_finalize_kernel, out);
}

// round 8
// speedup vs baseline: 1.0626x; 1.0626x over previous
#include <cuda_runtime.h>
#include <math.h>

// Shapes fixed by the problem instance.
#define B_SZ 2048
#define P_SZ 4
#define N_SZ 128
#define D_SZ 1024
#define S_SZ (N_SZ + 1)      // 129 samples: [last positive, negatives...]
#define EPS_F 1e-6f

#define THREADS 256
#define NWARP (THREADS / 32)

#define HALF0_END 65         // block h=0: samples [0,65); h=1: samples [65,129)
#define MAX_LOCAL 65

// Per-(batch, half) softmax partials: {m, sumexp, sim0, unused}
__device__ float4 g_part[B_SZ][2];

__global__ __launch_bounds__(THREADS)
void contrastive_sim_kernel(const float* __restrict__ anchor,
                            const float* __restrict__ positives,
                            const float* __restrict__ negatives) {
    const int b    = blockIdx.x;
    const int h    = blockIdx.y;
    const int tid  = threadIdx.x;
    const int warp = tid >> 5;
    const int lane = tid & 31;

    const int s_begin = h ? HALF0_END : 0;
    const int s_end   = h ? S_SZ : HALF0_END;
    const int n_local = s_end - s_begin;

    __shared__ float4 sa[D_SZ / 4];        // anchor row, 4 KB
    __shared__ float  sims[MAX_LOCAL];
    __shared__ float  red[NWARP];
    __shared__ float  s_na;

    // ---- load anchor into smem, accumulate ||a||^2 ----
    const float4* ap = reinterpret_cast<const float4*>(anchor + (size_t)b * D_SZ);
    float asq = 0.f;
    #pragma unroll
    for (int i = tid; i < D_SZ / 4; i += THREADS) {
        float4 v = ap[i];
        sa[i] = v;
        asq += v.x * v.x + v.y * v.y + v.z * v.z + v.w * v.w;
    }
    #pragma unroll
    for (int o = 16; o; o >>= 1) asq += __shfl_down_sync(0xffffffffu, asq, o);
    if (lane == 0) red[warp] = asq;
    __syncthreads();
    if (warp == 0) {
        float v = (lane < NWARP) ? red[lane] : 0.f;
        #pragma unroll
        for (int o = 16; o; o >>= 1) v += __shfl_down_sync(0xffffffffu, v, o);
        if (lane == 0) s_na = fmaxf(sqrtf(v), EPS_F);
    }
    __syncthreads();
    const float na = s_na;

    // ---- each warp: cosine sim for its share of this half's samples ----
    for (int s = s_begin + warp; s < s_end; s += NWARP) {
        const float4* xp;
        if (s == 0)
            xp = reinterpret_cast<const float4*>(
                positives + ((size_t)b * P_SZ + (P_SZ - 1)) * D_SZ);
        else
            xp = reinterpret_cast<const float4*>(
                negatives + ((size_t)b * N_SZ + (s - 1)) * D_SZ);

        float dot = 0.f, nsq = 0.f;
        #pragma unroll
        for (int i = 0; i < D_SZ / 4 / 32; i++) {   // 8 coalesced float4 loads/lane
            int idx = i * 32 + lane;
            float4 x = xp[idx];
            float4 a = sa[idx];
            dot += a.x * x.x + a.y * x.y + a.z * x.z + a.w * x.w;
            nsq += x.x * x.x + x.y * x.y + x.z * x.z + x.w * x.w;
        }
        #pragma unroll
        for (int o = 16; o; o >>= 1) {
            dot += __shfl_down_sync(0xffffffffu, dot, o);
            nsq += __shfl_down_sync(0xffffffffu, nsq, o);
        }
        if (lane == 0) {
            float ns = fmaxf(sqrtf(nsq), EPS_F);
            sims[s - s_begin] = dot / (na * ns);
        }
    }
    __syncthreads();

    // ---- warp 0: local softmax partial (m, sum_exp) over this half ----
    if (warp == 0) {
        float m = -1e30f;
        for (int s = lane; s < n_local; s += 32) m = fmaxf(m, sims[s]);
        #pragma unroll
        for (int o = 16; o; o >>= 1) m = fmaxf(m, __shfl_xor_sync(0xffffffffu, m, o));
        float sum = 0.f;
        for (int s = lane; s < n_local; s += 32) sum += __expf(sims[s] - m);
        #pragma unroll
        for (int o = 16; o; o >>= 1) sum += __shfl_xor_sync(0xffffffffu, sum, o);
        if (lane == 0) {
            float sim0 = (h == 0) ? sims[0] : 0.f;
            g_part[b][h] = make_float4(m, sum, sim0, 0.f);
        }
    }
}

__global__ __launch_bounds__(256)
void contrastive_reduce_kernel(float* __restrict__ out) {
    const int tid  = threadIdx.x;
    const int warp = tid >> 5;
    const int lane = tid & 31;
    __shared__ float red[8];

    float s = 0.f;
    for (int b = tid; b < B_SZ; b += 256) {
        float4 p0 = g_part[b][0];
        float4 p1 = g_part[b][1];
        float m = fmaxf(p0.x, p1.x);
        float S = p0.y * __expf(p0.x - m) + p1.y * __expf(p1.x - m);
        s += -(p0.z - m - __logf(S));
    }
    #pragma unroll
    for (int o = 16; o; o >>= 1) s += __shfl_down_sync(0xffffffffu, s, o);
    if (lane == 0) red[warp] = s;
    __syncthreads();
    if (warp == 0) {
        float v = (lane < 8) ? red[lane] : 0.f;
        #pragma unroll
        for (int o = 16; o; o >>= 1) v += __shfl_down_sync(0xffffffffu, v, o);
        if (lane == 0) *out = v / (float)B_SZ;
    }
}

extern "C" void kernel_launch(void* const* d_in, const int* in_sizes, int n_in,
                              void* d_out, int out_size) {
    const float* anchor    = (const float*)d_in[0];
    const float* positives = (const float*)d_in[1];
    const float* negatives = (const float*)d_in[2];
    float* out = (float*)d_out;

    contrastive_sim_kernel<<<dim3(B_SZ, 2), THREADS>>>(anchor, positives, negatives);
    contrastive_reduce_kernel<<<1, 256>>>(out);
}